// round 15
// baseline (speedup 1.0000x reference)
#include <cuda_runtime.h>

#define T_STEPS 2048
#define BATCH   2048
#define HID     32
#define NWARP   14
#define NTHD    448
#define NCTA    148

typedef unsigned long long u64;

#define S_SIG  (-1.4426950408889634f)   /* -log2(e)   */
#define S_TNH  (-2.8853900817779268f)   /* -2*log2(e) */

// ---- packed f32x2 helpers ----
__device__ __forceinline__ u64 ffma2(u64 a, u64 b, u64 c) {
    u64 d;
    asm("fma.rn.f32x2 %0, %1, %2, %3;" : "=l"(d) : "l"(a), "l"(b), "l"(c));
    return d;
}
__device__ __forceinline__ u64 pack2(float lo, float hi) {
    u64 d;
    asm("mov.b64 %0, {%1, %2};" : "=l"(d) : "f"(lo), "f"(hi));
    return d;
}
__device__ __forceinline__ void unpack2(u64 v, float& lo, float& hi) {
    asm("mov.b64 {%0, %1}, %2;" : "=f"(lo), "=f"(hi) : "l"(v));
}
__device__ __forceinline__ float ex2f(float x) {
    float y; asm("ex2.approx.f32 %0, %1;" : "=f"(y) : "f"(x)); return y;
}
__device__ __forceinline__ float rcpf(float x) {
    float y; asm("rcp.approx.f32 %0, %1;" : "=f"(y) : "f"(x)); return y;
}
__device__ __forceinline__ void stg32_pred(int pred, float* p, float a) {
    asm volatile("{\n\t"
                 ".reg .pred p;\n\t"
                 "setp.ne.u32 p, %0, 0;\n\t"
                 "@p st.global.f32 [%1], %2;\n\t"
                 "}" :: "r"(pred), "l"(p), "f"(a) : "memory");
}

__global__ void __launch_bounds__(NTHD, 1) lstm_kernel(
    const float* __restrict__ x,      // [T, B, 1]
    const float* __restrict__ W_ih,   // [4H, 1]
    const float* __restrict__ W_hh,   // [4H, H]
    const float* __restrict__ b_ih,   // [4H]
    const float* __restrict__ b_hh,   // [4H]
    const float* __restrict__ W_out,  // [1, H]
    const float* __restrict__ b_out,  // [1]
    float* __restrict__ out,          // [T*B] outs, then [B*H] hT, then [B*H] cT
    int out_size)
{
    const int lane = threadIdx.x & 31;
    const int wid  = threadIdx.x >> 5;
    const int gw   = blockIdx.x * NWARP + wid;   // 0..2071; warp <-> batch

    // o-gate weights, CTA-shared (pre-scaled by S_SIG), padded to kill conflicts.
    // wsm[p][j] = packed pair (W_hh[96+j][2p], W_hh[96+j][2p+1]) * S_SIG
    __shared__ __align__(16) u64  wsm[16][33];
    // per-warp h staging, double-buffered (broadcast reads -> no crossbar cost)
    __shared__ __align__(16) float shh[NWARP][2][32];

    for (int i = threadIdx.x; i < 512; i += NTHD) {
        const int p = i >> 5, j = i & 31;
        const float* wr = W_hh + (3 * HID + j) * HID + 2 * p;
        wsm[p][j] = pack2(wr[0] * S_SIG, wr[1] * S_SIG);
    }
    __syncthreads();

    if (gw >= BATCH) return;                  // 24 dummy warps exit
    const int b = gw;

    // gates i,f,g in registers (96 regs), pre-scaled (i,f: S_SIG; g: S_TNH)
    u64 w2[3][16];
    float wih[4], bias[4];
    #pragma unroll
    for (int g = 0; g < 3; g++) {
        const int row = g * 32 + lane;
        const float s = (g == 2) ? S_TNH : S_SIG;
        const float* wr = W_hh + row * HID;
        #pragma unroll
        for (int p = 0; p < 16; p++)
            w2[g][p] = pack2(wr[2 * p] * s, wr[2 * p + 1] * s);
        wih[g]  = W_ih[row] * s;
        bias[g] = (b_ih[row] + b_hh[row]) * s;
    }
    {   // o-gate scalars (weights come from smem in the loop)
        const int row = 3 * HID + lane;
        wih[3]  = W_ih[row] * S_SIG;
        bias[3] = (b_ih[row] + b_hh[row]) * S_SIG;
    }
    const float wout = W_out[lane];
    const float bout = b_out[0];

    float h = 0.f, c = 0.f, rp = 0.f;         // state + deferred output partial

    const float* xp = x + b;
    float xv = *xp;
    float* outp = out + b;
    const int store_pred = (lane == 0);

    shh[wid][0][lane] = 0.f;                  // h(-1)
    __syncwarp();

    #pragma unroll 2
    for (int t = 0; t < T_STEPS; t++) {
        const int buf = t & 1;

        // init gate accumulators: lo = x*wih + bias, hi = 0
        u64 acc[4];
        #pragma unroll
        for (int g = 0; g < 4; g++)
            acc[g] = pack2(fmaf(xv, wih[g], bias[g]), 0.f);

        // deferred reduction of step t-1 output partial (hidden under matvec)
        float r = rp;
        #pragma unroll
        for (int off = 16; off; off >>= 1)
            r += __shfl_xor_sync(0xffffffffu, r, off);

        // clamped prefetch of next x
        const float* xpn = (t < T_STEPS - 1) ? (xp + BATCH) : xp;
        float xnext = *xpn;
        xp = xpn;

        // recurrent matvec: 64 FFMA2 (3 reg-gates + smem o-gate)
        const double2* hp = reinterpret_cast<const double2*>(shh[wid][buf]);
        #pragma unroll
        for (int q = 0; q < 8; q++) {
            double2 v = hp[q];                       // LDS.128 broadcast
            u64 p0 = __double_as_longlong(v.x), p1 = __double_as_longlong(v.y);
            u64 wo0 = wsm[2 * q][lane];              // LDS.64 lane-indexed
            u64 wo1 = wsm[2 * q + 1][lane];
            acc[0] = ffma2(p0, w2[0][2 * q], acc[0]);
            acc[1] = ffma2(p0, w2[1][2 * q], acc[1]);
            acc[2] = ffma2(p0, w2[2][2 * q], acc[2]);
            acc[3] = ffma2(p0, wo0,          acc[3]);
            acc[0] = ffma2(p1, w2[0][2 * q + 1], acc[0]);
            acc[1] = ffma2(p1, w2[1][2 * q + 1], acc[1]);
            acc[2] = ffma2(p1, w2[2][2 * q + 1], acc[2]);
            acc[3] = ffma2(p1, wo1,              acc[3]);
        }

        // store out[t-1] (placeholder at t==0, overwritten by t==1's store)
        stg32_pred(store_pred, outp, r + bout);
        outp += (t > 0) ? BATCH : 0;

        // horizontal adds
        float v0, v1, v2, v3;
        {
            float lo, hi;
            unpack2(acc[0], lo, hi); v0 = lo + hi;
            unpack2(acc[1], lo, hi); v1 = lo + hi;
            unpack2(acc[2], lo, hi); v2 = lo + hi;
            unpack2(acc[3], lo, hi); v3 = lo + hi;
        }

        // quad-shared-rcp gates
        float ig, fg, og, gg;
        {
            float Ei = ex2f(v0), Ef = ex2f(v1), Eg = ex2f(v2), Eo = ex2f(v3);
            float Pi = 1.f + Ei, Pf = 1.f + Ef, Pg = 1.f + Eg, Po = 1.f + Eo;
            float Pif = Pi * Pf, Pgo = Pg * Po;
            float R = rcpf(Pif * Pgo);
            float PgoR = Pgo * R, PifR = Pif * R;
            ig = Pf * PgoR;
            fg = Pi * PgoR;
            og = PifR * Pg;
            gg = fmaf(2.f, PifR * Po, -1.f);
        }
        c = fmaf(fg, c, ig * gg);
        {
            float a = fminf(c * S_TNH, 63.f);    // clamp avoids inf/NaN path
            float T = 1.f + ex2f(a);
            h = og * fmaf(2.f, rcpf(T), -1.f);
        }

        // publish h(t) for next step's matvec
        shh[wid][buf ^ 1][lane] = h;
        rp = h * wout;
        xv = xnext;
        __syncwarp();
    }

    // epilogue: reduce final step partial -> out[T-1] (outp already at row T-1)
    {
        float r = rp;
        #pragma unroll
        for (int off = 16; off; off >>= 1)
            r += __shfl_xor_sync(0xffffffffu, r, off);
        stg32_pred(store_pred, outp, r + bout);
    }

    // final state (hT, cT)
    if (out_size >= T_STEPS * BATCH + 2 * BATCH * HID) {
        float* hT = out + (size_t)T_STEPS * BATCH;
        float* cT = hT + BATCH * HID;
        hT[(size_t)b * HID + lane] = h;
        cT[(size_t)b * HID + lane] = c;
    }
}

extern "C" void kernel_launch(void* const* d_in, const int* in_sizes, int n_in,
                              void* d_out, int out_size) {
    const float* x     = (const float*)d_in[0];
    const float* W_ih  = (const float*)d_in[1];
    const float* W_hh  = (const float*)d_in[2];
    const float* b_ih  = (const float*)d_in[3];
    const float* b_hh  = (const float*)d_in[4];
    const float* W_out = (const float*)d_in[5];
    const float* b_out = (const float*)d_in[6];
    float* out = (float*)d_out;

    // 148 CTAs x 448 threads = 2072 warps, ONE independent batch per warp,
    // single wave on all 148 SMs, 3-4 warps/SMSP, no cross-warp sync in loop.
    lstm_kernel<<<NCTA, NTHD>>>(x, W_ih, W_hh, b_ih, b_hh, W_out, b_out, out, out_size);
}